// round 11
// baseline (speedup 1.0000x reference)
#include <cuda_runtime.h>
#include <cuda_fp16.h>
#include <float.h>
#include <stdint.h>

// Problem constants
#define CD   256
#define ZTHW 8192
#define NPT  32768
#define NK   1024

// Output layout (float32). OFF_D is ODD -> only scalar stores in d region.
#define OFF_ZQ   0
#define OFF_LOSS 8388608
#define OFF_INDS 8388609
#define OFF_D    8421377

#define GAP_THRESH  1e-4f    // flag threshold on fp16-path top-2 gap
#define CAND_MARGIN 4e-4f    // refine candidate margin (>=8 sigma of d-noise)

// Scratch globals
__device__ __align__(16) __half g_zth[NPT * CD];   // z^T fp16 [n][c]
__device__ __align__(16) __half g_Eh[NK * CD];     // E fp16 [k][c]
__device__ float  g_xn4[4][NPT];                   // per-64ch xnorm partials
__device__ float  g_xnorm[NPT];
__device__ float  g_enorm[NK];
__device__ int    g_inds[NPT];
__device__ double g_part[512];
__device__ int    g_nflag;
__device__ int    g_flag[NPT];

// ---------------------------------------------------------------------------
// PTX helpers (portable sm_80+: mma.sync / ldmatrix / cp.async)
// ---------------------------------------------------------------------------
__device__ __forceinline__ uint32_t smem_u32(const void* p) {
    uint32_t a;
    asm("{ .reg .u64 t; cvta.to.shared.u64 t, %1; cvt.u32.u64 %0, t; }" : "=r"(a) : "l"(p));
    return a;
}
__device__ __forceinline__ void ldsm_x4(uint32_t& r0, uint32_t& r1, uint32_t& r2,
                                        uint32_t& r3, uint32_t addr) {
    asm volatile("ldmatrix.sync.aligned.m8n8.x4.shared.b16 {%0,%1,%2,%3}, [%4];"
                 : "=r"(r0), "=r"(r1), "=r"(r2), "=r"(r3) : "r"(addr));
}
__device__ __forceinline__ void mma16816(float* c, const uint32_t* a, const uint32_t* b) {
    asm volatile(
        "mma.sync.aligned.m16n8k16.row.col.f32.f16.f16.f32 "
        "{%0,%1,%2,%3}, {%4,%5,%6,%7}, {%8,%9}, {%0,%1,%2,%3};"
        : "+f"(c[0]), "+f"(c[1]), "+f"(c[2]), "+f"(c[3])
        : "r"(a[0]), "r"(a[1]), "r"(a[2]), "r"(a[3]), "r"(b[0]), "r"(b[1]));
}
__device__ __forceinline__ void cp16(uint32_t dst, const void* src) {
    asm volatile("cp.async.cg.shared.global [%0], [%1], 16;" :: "r"(dst), "l"(src));
}
#define CP_COMMIT() asm volatile("cp.async.commit_group;" ::: "memory")
#define CP_WAIT(N)  asm volatile("cp.async.wait_group %0;" :: "n"(N) : "memory")

// GEMM smem layout (bytes) -- 2 CTAs/SM (2 x ~106.5KB < 228KB)
#define APAD   264                    // 256 halves + 8 pad (row stride 528B)
#define EPAD   72                    // 64 halves + 8 pad  (row stride 144B)
#define A_PLANE (128 * APAD * 2)      // 67584
#define SM_A    0
#define SM_E    A_PLANE               // 67584; 2 bufs x 128 x 144 = 36864
#define E_BUF   (128 * EPAD * 2)      // 18432
#define SM_XN   (SM_E + 2 * E_BUF)    // 104448 (128 floats)
#define SM_EN   (SM_XN + 512)         // 104960 (1024 floats enorm cache)
#define SM_TOT  (SM_EN + 4096)        // 109056

// ---------------------------------------------------------------------------
// Transpose z -> fp16 [N][C]  +  per-block xnorm partials (fused).
// ---------------------------------------------------------------------------
__global__ __launch_bounds__(256) void conv_z(const float* __restrict__ z) {
    __shared__ float tile[64][65];
    const int bx = blockIdx.x;
    const int ct = bx & 3, tt = (bx >> 2) & 127, b = bx >> 9;
    const int tid = threadIdx.x;

    const int c_l = tid >> 4, t4 = (tid & 15) << 2;
    #pragma unroll
    for (int cc = 0; cc < 4; cc++) {
        const int c_idx = cc * 16 + c_l;
        const float4 v = *(const float4*)&z[((size_t)(b * CD + ct * 64 + c_idx)) * ZTHW
                                            + tt * 64 + t4];
        tile[c_idx][t4 + 0] = v.x; tile[c_idx][t4 + 1] = v.y;
        tile[c_idx][t4 + 2] = v.z; tile[c_idx][t4 + 3] = v.w;
    }
    __syncthreads();

    const int t_l = tid >> 2, cs = (tid & 3) << 4;
    const size_t n = (size_t)b * ZTHW + tt * 64 + t_l;
    __half h[16];
    float sq = 0.f;
    #pragma unroll
    for (int j = 0; j < 16; j++) {
        const float x = tile[cs + j][t_l];
        h[j] = __float2half_rn(x);
        sq = fmaf(x, x, sq);
    }
    __half* dh = g_zth + n * CD + ct * 64 + cs;
    *(uint4*)(dh + 0) = ((uint4*)h)[0];  *(uint4*)(dh + 8) = ((uint4*)h)[1];

    sq += __shfl_xor_sync(0xFFFFFFFFu, sq, 1);
    sq += __shfl_xor_sync(0xFFFFFFFFu, sq, 2);
    if ((tid & 3) == 0) g_xn4[ct][n] = sq;
}

__global__ void xnorm_finish(void) {
    const int p = blockIdx.x * blockDim.x + threadIdx.x;
    g_xnorm[p] = (g_xn4[0][p] + g_xn4[1][p]) + (g_xn4[2][p] + g_xn4[3][p]);
}

// ---------------------------------------------------------------------------
// E -> fp16 + enorm (fused; warp per code row). Also zeroes g_nflag.
// ---------------------------------------------------------------------------
__global__ void conv_E(const float* __restrict__ E) {
    const int gt = blockIdx.x * blockDim.x + threadIdx.x;
    if (gt == 0) g_nflag = 0;
    const int row = gt >> 5, lane = gt & 31;
    if (row >= NK) return;
    const float* er = E + (size_t)row * CD;
    float s = 0.f;
    #pragma unroll
    for (int i = 0; i < 2; i++) {
        const int c = i * 128 + lane * 4;
        const float4 v = *(const float4*)&er[c];
        __half h[4] = {__float2half_rn(v.x), __float2half_rn(v.y),
                       __float2half_rn(v.z), __float2half_rn(v.w)};
        *(uint2*)&g_Eh[(size_t)row * CD + c] = *(uint2*)h;
        s = fmaf(v.x, v.x, s); s = fmaf(v.y, v.y, s);
        s = fmaf(v.z, v.z, s); s = fmaf(v.w, v.w, s);
    }
    #pragma unroll
    for (int off = 16; off; off >>= 1) s += __shfl_xor_sync(0xFFFFFFFFu, s, off);
    if (lane == 0) g_enorm[row] = s;
}

// ---------------------------------------------------------------------------
// mma.sync GEMM: 512 threads (16 warps, 4x4 warp grid, 32x32 warp tile),
// 2 CTAs/SM -> 32 warps/SM. CTA = 128 pts x 128 codes/ct-tile, 8 ct tiles.
// fp16 z resident; E streamed (cp.async dbl-buffer). Top-2 + gap flagging.
// ---------------------------------------------------------------------------
extern __shared__ char dsm[];

__global__ void __launch_bounds__(512, 2) vq_gemm_mma(float* __restrict__ out) {
    const uint32_t smu = smem_u32(dsm);
    const int tid = threadIdx.x;
    const int lane = tid & 31, wid = tid >> 5;
    const int wy = wid >> 2, wx = wid & 3;          // 4x4 warp grid
    const int n0 = blockIdx.x * 128;

    float* xn_sm = (float*)(dsm + SM_XN);
    float* en_sm = (float*)(dsm + SM_EN);
    if (tid < 128) xn_sm[tid] = g_xnorm[n0 + tid];
    #pragma unroll
    for (int i = 0; i < 2; i++) en_sm[i * 512 + tid] = g_enorm[i * 512 + tid];

    // Resident A (128 rows x 512B) + E stage 0; one cp.async group.
    {
        #pragma unroll
        for (int it = 0; it < 8; it++) {
            const int id = it * 512 + tid;           // 0..4095 16B chunks
            const int row = id >> 5;
            const int ch  = id & 31;
            cp16(smu + SM_A + row * (APAD * 2) + ch * 16,
                 g_zth + (size_t)(n0 + row) * CD + ch * 8);
        }
        #pragma unroll
        for (int it = 0; it < 2; it++) {
            const int id = it * 512 + tid;           // 0..1023
            const int code = id >> 3, ch = id & 7;   // stage0: ct=0, kq=0
            cp16(smu + SM_E + code * (EPAD * 2) + ch * 16,
                 g_Eh + (size_t)code * CD + ch * 8);
        }
        CP_COMMIT();
    }

    const uint32_t aBase = smu + SM_A + (wy * 32 + (lane & 15)) * (APAD * 2)
                           + ((lane & 16) ? 16 : 0);
    const uint32_t bBase = smu + SM_E
                           + (wx * 32 + (lane & 7) + ((lane & 16) ? 8 : 0)) * (EPAD * 2)
                           + ((lane & 8) ? 16 : 0);

    float acc[2][4][4];
    float best[4], sec[4];
    int   bidr[4];
    #pragma unroll
    for (int i = 0; i < 4; i++) { best[i] = FLT_MAX; sec[i] = FLT_MAX; bidr[i] = 0; }

    for (int s = 0; s < 32; s++) {                   // stage = ct*4 + kq
        const int ct = s >> 2, kq = s & 3, buf = s & 1;
        if ((s & 3) == 0) {
            #pragma unroll
            for (int mt = 0; mt < 2; mt++)
                #pragma unroll
                for (int nt = 0; nt < 4; nt++)
                    #pragma unroll
                    for (int c = 0; c < 4; c++) acc[mt][nt][c] = 0.f;
        }
        if (s < 31) {
            const int ns = s + 1;
            const int nct = ns >> 2, nkq = ns & 3, nbuf = ns & 1;
            #pragma unroll
            for (int it = 0; it < 2; it++) {
                const int id = it * 512 + tid;
                const int code = id >> 3, ch = id & 7;
                cp16(smu + SM_E + nbuf * E_BUF + code * (EPAD * 2) + ch * 16,
                     g_Eh + (size_t)(nct * 128 + code) * CD + nkq * 64 + ch * 8);
            }
            CP_COMMIT();
            CP_WAIT(1);
        } else {
            CP_WAIT(0);
        }
        __syncthreads();

        #pragma unroll
        for (int step = 0; step < 4; step++) {
            const int kh_abs = kq * 64 + step * 16;
            const int kh_loc = step * 16;
            uint32_t bf[4][2];
            #pragma unroll
            for (int p4 = 0; p4 < 2; p4++) {
                uint32_t r0, r1, r2, r3;
                ldsm_x4(r0, r1, r2, r3,
                        bBase + buf * E_BUF + p4 * 16 * (EPAD * 2) + kh_loc * 2);
                bf[p4 * 2][0] = r0; bf[p4 * 2][1] = r1;
                bf[p4 * 2 + 1][0] = r2; bf[p4 * 2 + 1][1] = r3;
            }
            uint32_t af[2][4];
            #pragma unroll
            for (int mt = 0; mt < 2; mt++)
                ldsm_x4(af[mt][0], af[mt][1], af[mt][2], af[mt][3],
                        aBase + mt * 16 * (APAD * 2) + kh_abs * 2);
            #pragma unroll
            for (int mt = 0; mt < 2; mt++)
                #pragma unroll
                for (int nt = 0; nt < 4; nt++)
                    mma16816(acc[mt][nt], af[mt], bf[nt]);
        }

        if ((s & 3) == 3) {
            const int k0 = ct * 128;
            #pragma unroll
            for (int mt = 0; mt < 2; mt++) {
                #pragma unroll
                for (int rsel = 0; rsel < 2; rsel++) {
                    const int bi_ = mt * 2 + rsel;
                    const int row = wy * 32 + mt * 16 + rsel * 8 + (lane >> 2);
                    const float xnv = xn_sm[row];
                    float* dr = out + OFF_D + (size_t)(n0 + row) * NK + k0;
                    #pragma unroll
                    for (int nt = 0; nt < 4; nt++) {
                        const int col0 = wx * 32 + nt * 8 + 2 * (lane & 3);
                        const float d0 = xnv + en_sm[k0 + col0]
                                       - 2.0f * acc[mt][nt][rsel * 2];
                        const float d1 = xnv + en_sm[k0 + col0 + 1]
                                       - 2.0f * acc[mt][nt][rsel * 2 + 1];
                        dr[col0] = d0;
                        dr[col0 + 1] = d1;
                        if (d0 < best[bi_]) { sec[bi_] = best[bi_]; best[bi_] = d0; bidr[bi_] = k0 + col0; }
                        else if (d0 < sec[bi_]) sec[bi_] = d0;
                        if (d1 < best[bi_]) { sec[bi_] = best[bi_]; best[bi_] = d1; bidr[bi_] = k0 + col0 + 1; }
                        else if (d1 < sec[bi_]) sec[bi_] = d1;
                    }
                }
            }
        }
        __syncthreads();
    }

    // quad reduce (lanes differing in bits 0-1 share rows): top-2 merge
    #pragma unroll
    for (int i = 0; i < 4; i++) {
        #pragma unroll
        for (int off = 1; off <= 2; off <<= 1) {
            const float v1o = __shfl_xor_sync(0xFFFFFFFFu, best[i], off);
            const int   i1o = __shfl_xor_sync(0xFFFFFFFFu, bidr[i], off);
            const float v2o = __shfl_xor_sync(0xFFFFFFFFu, sec[i], off);
            if (v1o < best[i] || (v1o == best[i] && i1o < bidr[i])) {
                sec[i]  = fminf(best[i], v2o);
                best[i] = v1o; bidr[i] = i1o;
            } else {
                sec[i] = fminf(sec[i], v1o);
            }
        }
    }
    // cross-warp reduce: 4 warps (wx 0..3) share each row group. wx!=0 write
    // triples to smem; wx==0 merges in ascending wx order (lexicographic min
    // + proper second -> order-independent, first-index-wins preserved).
    float* sv1 = (float*)(dsm + SM_E);
    int*   si1 = (int*)(dsm + SM_E + 2048);
    float* sv2 = (float*)(dsm + SM_E + 4096);
    if (wx != 0 && (lane & 3) == 0) {
        #pragma unroll
        for (int i = 0; i < 4; i++) {
            const int row = wy * 32 + (i >> 1) * 16 + (i & 1) * 8 + (lane >> 2);
            const int idx = (wx - 1) * 128 + row;
            sv1[idx] = best[i]; si1[idx] = bidr[i]; sv2[idx] = sec[i];
        }
    }
    __syncthreads();
    if (wx == 0 && (lane & 3) == 0) {
        #pragma unroll
        for (int i = 0; i < 4; i++) {
            const int row = wy * 32 + (i >> 1) * 16 + (i & 1) * 8 + (lane >> 2);
            float v1 = best[i], v2 = sec[i]; int i1 = bidr[i];
            #pragma unroll
            for (int o = 0; o < 3; o++) {
                const float o1 = sv1[o * 128 + row], o2 = sv2[o * 128 + row];
                const int   oi = si1[o * 128 + row];
                if (o1 < v1 || (o1 == v1 && oi < i1)) {
                    v2 = fminf(v1, o2); v1 = o1; i1 = oi;
                } else {
                    v2 = fminf(v2, o1);
                }
            }
            const int n = n0 + row;
            g_inds[n] = i1;
            out[OFF_INDS + n] = (float)i1;
            if (v2 - v1 < GAP_THRESH) {
                int slot = atomicAdd(&g_nflag, 1);
                g_flag[slot] = n;
            }
        }
    }
}

// ---------------------------------------------------------------------------
// Refine v2: candidates from the written d row within CAND_MARGIN of its min,
// recomputed exactly in fp32; lexicographic (d, k) min. ~10KB/point traffic.
// ---------------------------------------------------------------------------
__global__ __launch_bounds__(256) void vq_refine(const float* __restrict__ z,
                                                 const float* __restrict__ E,
                                                 float* __restrict__ out) {
    __shared__ float zs[256];
    __shared__ float rv[8];
    __shared__ int   ri[8];
    __shared__ int   cand[64];
    __shared__ int   ncand;
    const int nf = g_nflag;
    const int tid = threadIdx.x, w = tid >> 5, lane = tid & 31;

    for (int f = blockIdx.x; f < nf; f += gridDim.x) {
        const int p = g_flag[f];
        const int b = p >> 13, thw = p & (ZTHW - 1);
        const float* zp = z + (size_t)b * CD * ZTHW + thw;
        zs[tid] = zp[(size_t)tid * ZTHW];
        if (tid == 0) ncand = 0;
        __syncthreads();

        const float* drow = out + OFF_D + (size_t)p * NK;
        float bv = FLT_MAX;
        float dv[4];
        #pragma unroll
        for (int j = 0; j < 4; j++) {
            dv[j] = drow[j * 256 + tid];
            bv = fminf(bv, dv[j]);
        }
        #pragma unroll
        for (int off = 16; off; off >>= 1)
            bv = fminf(bv, __shfl_xor_sync(0xFFFFFFFFu, bv, off));
        if (lane == 0) rv[w] = bv;
        __syncthreads();
        if (tid == 0) {
            float v = rv[0];
            #pragma unroll
            for (int w2 = 1; w2 < 8; w2++) v = fminf(v, rv[w2]);
            rv[0] = v;
        }
        __syncthreads();
        const float vmin = rv[0];

        #pragma unroll
        for (int j = 0; j < 4; j++) {
            if (dv[j] < vmin + CAND_MARGIN) {
                const int s = atomicAdd(&ncand, 1);
                if (s < 64) cand[s] = j * 256 + tid;
            }
        }
        __syncthreads();
        const int nc = min(ncand, 64);

        float cbv = FLT_MAX; int cbi = 0x7FFFFFFF;
        const float xn = g_xnorm[p];
        for (int ci = w; ci < nc; ci += 8) {
            const int k = cand[ci];
            const float* er = E + (size_t)k * CD;
            float dot = 0.f;
            #pragma unroll
            for (int i = 0; i < 8; i++)
                dot = fmaf(er[lane + 32 * i], zs[lane + 32 * i], dot);
            #pragma unroll
            for (int off = 16; off; off >>= 1)
                dot += __shfl_xor_sync(0xFFFFFFFFu, dot, off);
            const float d = xn + g_enorm[k] - 2.0f * dot;
            if (d < cbv || (d == cbv && k < cbi)) { cbv = d; cbi = k; }
        }
        if (lane == 0) { rv[w] = cbv; ri[w] = cbi; }
        __syncthreads();
        if (tid == 0) {
            float v = rv[0]; int id = ri[0];
            #pragma unroll
            for (int w2 = 1; w2 < 8; w2++)
                if (rv[w2] < v || (rv[w2] == v && ri[w2] < id)) { v = rv[w2]; id = ri[w2]; }
            g_inds[p] = id;
            out[OFF_INDS + p] = (float)id;
        }
        __syncthreads();
    }
}

// ---------------------------------------------------------------------------
// Gather z_q, z_q_ste = z + (z_q - z), deterministic loss partials.
// ---------------------------------------------------------------------------
__global__ __launch_bounds__(256) void vq_out(const float* __restrict__ z,
                                              const float* __restrict__ E,
                                              float* __restrict__ out) {
    int t = blockIdx.x * blockDim.x + threadIdx.x;
    int p = t >> 2, q = t & 3;
    int b = p >> 13, thw = p & (ZTHW - 1);
    const float* zp = z + (size_t)b * CD * ZTHW + thw;
    float* op = out + OFF_ZQ + (size_t)b * CD * ZTHW + thw;
    int row = g_inds[p];
    const float4* er = (const float4*)(E + (size_t)row * CD + q * 64);

    float local = 0.f;
    #pragma unroll 4
    for (int c4 = 0; c4 < 16; c4++) {
        float4 e4 = er[c4];
        float ev[4] = {e4.x, e4.y, e4.z, e4.w};
        #pragma unroll
        for (int j = 0; j < 4; j++) {
            int c = q * 64 + c4 * 4 + j;
            float zv = zp[(size_t)c * ZTHW];
            float tt = __fsub_rn(ev[j], zv);
            op[(size_t)c * ZTHW] = __fadd_rn(zv, tt);
            local = fmaf(tt, tt, local);
        }
    }
    #pragma unroll
    for (int off = 16; off; off >>= 1) local += __shfl_xor_sync(0xFFFFFFFFu, local, off);
    __shared__ float ws[8];
    int lane = threadIdx.x & 31, w = threadIdx.x >> 5;
    if (lane == 0) ws[w] = local;
    __syncthreads();
    if (threadIdx.x == 0) {
        double s = 0.0;
        #pragma unroll
        for (int i = 0; i < 8; i++) s += (double)ws[i];
        g_part[blockIdx.x] = s;
    }
}

__global__ void vq_finalize(float* __restrict__ out, int npart) {
    if (threadIdx.x == 0 && blockIdx.x == 0) {
        double s = 0.0;
        for (int i = 0; i < npart; i++) s += g_part[i];
        out[OFF_LOSS] = (float)(1.25 * s / 8388608.0);
    }
}

// ---------------------------------------------------------------------------
extern "C" void kernel_launch(void* const* d_in, const int* in_sizes, int n_in,
                              void* d_out, int out_size) {
    const float* z = (const float*)d_in[0];
    const float* E = (const float*)d_in[1];
    float* out = (float*)d_out;

    conv_z<<<2048, 256>>>(z);             // also emits xnorm partials
    conv_E<<<128, 256>>>(E);              // also emits enorm, zeroes g_nflag
    xnorm_finish<<<128, 256>>>();

    cudaFuncSetAttribute(vq_gemm_mma, cudaFuncAttributeMaxDynamicSharedMemorySize, SM_TOT);
    vq_gemm_mma<<<NPT / 128, 512, SM_TOT>>>(out);

    vq_refine<<<592, 256>>>(z, E, out);
    vq_out<<<512, 256>>>(z, E, out);
    vq_finalize<<<1, 32>>>(out, 512);
}

// round 12
// speedup vs baseline: 1.1381x; 1.1381x over previous
#include <cuda_runtime.h>
#include <cuda_fp16.h>
#include <float.h>
#include <stdint.h>

// Problem constants
#define CD   256
#define ZTHW 8192
#define NPT  32768
#define NK   1024

// Output layout (float32). OFF_D is ODD -> only scalar stores in d region.
#define OFF_ZQ   0
#define OFF_LOSS 8388608
#define OFF_INDS 8388609
#define OFF_D    8421377

#define GAP_THRESH  1e-4f    // flag threshold on fp16-path top-2 gap
#define CAND_MARGIN 4e-4f    // refine candidate margin (>=8 sigma of d-noise)

// Scratch globals
__device__ __align__(16) __half g_zth[NPT * CD];   // z^T fp16 [n][c]
__device__ __align__(16) __half g_Eh[NK * CD];     // E fp16 [k][c]
__device__ float  g_xn4[4][NPT];                   // per-64ch xnorm partials
__device__ float  g_enorm[NK];
__device__ int    g_inds[NPT];
__device__ double g_part[512];
__device__ int    g_nflag;
__device__ int    g_flag[NPT];

// ---------------------------------------------------------------------------
// PTX helpers (portable sm_80+: mma.sync / ldmatrix / cp.async)
// ---------------------------------------------------------------------------
__device__ __forceinline__ uint32_t smem_u32(const void* p) {
    uint32_t a;
    asm("{ .reg .u64 t; cvta.to.shared.u64 t, %1; cvt.u32.u64 %0, t; }" : "=r"(a) : "l"(p));
    return a;
}
__device__ __forceinline__ void ldsm_x4(uint32_t& r0, uint32_t& r1, uint32_t& r2,
                                        uint32_t& r3, uint32_t addr) {
    asm volatile("ldmatrix.sync.aligned.m8n8.x4.shared.b16 {%0,%1,%2,%3}, [%4];"
                 : "=r"(r0), "=r"(r1), "=r"(r2), "=r"(r3) : "r"(addr));
}
__device__ __forceinline__ void mma16816(float* c, const uint32_t* a, const uint32_t* b) {
    asm volatile(
        "mma.sync.aligned.m16n8k16.row.col.f32.f16.f16.f32 "
        "{%0,%1,%2,%3}, {%4,%5,%6,%7}, {%8,%9}, {%0,%1,%2,%3};"
        : "+f"(c[0]), "+f"(c[1]), "+f"(c[2]), "+f"(c[3])
        : "r"(a[0]), "r"(a[1]), "r"(a[2]), "r"(a[3]), "r"(b[0]), "r"(b[1]));
}
__device__ __forceinline__ void cp16(uint32_t dst, const void* src) {
    asm volatile("cp.async.cg.shared.global [%0], [%1], 16;" :: "r"(dst), "l"(src));
}
#define CP_COMMIT() asm volatile("cp.async.commit_group;" ::: "memory")
#define CP_WAIT(N)  asm volatile("cp.async.wait_group %0;" :: "n"(N) : "memory")

// GEMM smem layout (bytes) -- 2 CTAs/SM (2 x ~106.5KB < 228KB)
#define APAD   264                    // 256 halves + 8 pad (row stride 528B)
#define EPAD   72                     // 64 halves + 8 pad  (row stride 144B)
#define A_PLANE (128 * APAD * 2)      // 67584
#define SM_A    0
#define SM_E    A_PLANE               // 67584; 2 bufs x 128 x 144 = 36864
#define E_BUF   (128 * EPAD * 2)      // 18432
#define SM_XN   (SM_E + 2 * E_BUF)    // 104448 (128 floats)
#define SM_EN   (SM_XN + 512)         // 104960 (1024 floats enorm cache)
#define SM_TOT  (SM_EN + 4096)        // 109056

// ---------------------------------------------------------------------------
// Transpose z -> fp16 [N][C]  +  per-block xnorm partials (fused).
// ---------------------------------------------------------------------------
__global__ __launch_bounds__(256) void conv_z(const float* __restrict__ z) {
    __shared__ float tile[64][65];
    const int bx = blockIdx.x;
    const int ct = bx & 3, tt = (bx >> 2) & 127, b = bx >> 9;
    const int tid = threadIdx.x;

    const int c_l = tid >> 4, t4 = (tid & 15) << 2;
    #pragma unroll
    for (int cc = 0; cc < 4; cc++) {
        const int c_idx = cc * 16 + c_l;
        const float4 v = *(const float4*)&z[((size_t)(b * CD + ct * 64 + c_idx)) * ZTHW
                                            + tt * 64 + t4];
        tile[c_idx][t4 + 0] = v.x; tile[c_idx][t4 + 1] = v.y;
        tile[c_idx][t4 + 2] = v.z; tile[c_idx][t4 + 3] = v.w;
    }
    __syncthreads();

    const int t_l = tid >> 2, cs = (tid & 3) << 4;
    const size_t n = (size_t)b * ZTHW + tt * 64 + t_l;
    __half h[16];
    float sq = 0.f;
    #pragma unroll
    for (int j = 0; j < 16; j++) {
        const float x = tile[cs + j][t_l];
        h[j] = __float2half_rn(x);
        sq = fmaf(x, x, sq);
    }
    __half* dh = g_zth + n * CD + ct * 64 + cs;
    *(uint4*)(dh + 0) = ((uint4*)h)[0];  *(uint4*)(dh + 8) = ((uint4*)h)[1];

    sq += __shfl_xor_sync(0xFFFFFFFFu, sq, 1);
    sq += __shfl_xor_sync(0xFFFFFFFFu, sq, 2);
    if ((tid & 3) == 0) g_xn4[ct][n] = sq;
}

// xnorm from partials -- EXACT same add order everywhere: (0+1)+(2+3)
__device__ __forceinline__ float xnorm_of(int n) {
    return (g_xn4[0][n] + g_xn4[1][n]) + (g_xn4[2][n] + g_xn4[3][n]);
}

// ---------------------------------------------------------------------------
// E -> fp16 + enorm (fused; warp per code row). Also zeroes g_nflag.
// ---------------------------------------------------------------------------
__global__ void conv_E(const float* __restrict__ E) {
    const int gt = blockIdx.x * blockDim.x + threadIdx.x;
    if (gt == 0) g_nflag = 0;
    const int row = gt >> 5, lane = gt & 31;
    if (row >= NK) return;
    const float* er = E + (size_t)row * CD;
    float s = 0.f;
    #pragma unroll
    for (int i = 0; i < 2; i++) {
        const int c = i * 128 + lane * 4;
        const float4 v = *(const float4*)&er[c];
        __half h[4] = {__float2half_rn(v.x), __float2half_rn(v.y),
                       __float2half_rn(v.z), __float2half_rn(v.w)};
        *(uint2*)&g_Eh[(size_t)row * CD + c] = *(uint2*)h;
        s = fmaf(v.x, v.x, s); s = fmaf(v.y, v.y, s);
        s = fmaf(v.z, v.z, s); s = fmaf(v.w, v.w, s);
    }
    #pragma unroll
    for (int off = 16; off; off >>= 1) s += __shfl_xor_sync(0xFFFFFFFFu, s, off);
    if (lane == 0) g_enorm[row] = s;
}

// ---------------------------------------------------------------------------
// mma.sync GEMM: 128 threads (4 warps, 2x2 grid, 64x64 warp tile), 2 CTAs/SM.
// Per step: 8 ldsm feed 32 independent MMAs (128 B/mma smem traffic).
// fp16 z resident; E streamed (cp.async dbl-buffer). Top-2 + gap flagging.
// ---------------------------------------------------------------------------
extern __shared__ char dsm[];

__global__ void __launch_bounds__(128, 2) vq_gemm_mma(float* __restrict__ out) {
    const uint32_t smu = smem_u32(dsm);
    const int tid = threadIdx.x;
    const int lane = tid & 31, wid = tid >> 5;
    const int wy = wid >> 1, wx = wid & 1;          // 2x2 warp grid
    const int n0 = blockIdx.x * 128;

    float* xn_sm = (float*)(dsm + SM_XN);
    float* en_sm = (float*)(dsm + SM_EN);
    xn_sm[tid] = xnorm_of(n0 + tid);
    #pragma unroll
    for (int i = 0; i < 8; i++) en_sm[i * 128 + tid] = g_enorm[i * 128 + tid];

    // Resident A (128 rows x 512B) + E stage 0; one cp.async group.
    {
        #pragma unroll
        for (int it = 0; it < 32; it++) {
            const int id = it * 128 + tid;           // 0..4095 16B chunks
            const int row = id >> 5;
            const int ch  = id & 31;
            cp16(smu + SM_A + row * (APAD * 2) + ch * 16,
                 g_zth + (size_t)(n0 + row) * CD + ch * 8);
        }
        #pragma unroll
        for (int it = 0; it < 8; it++) {
            const int id = it * 128 + tid;           // 0..1023
            const int code = id >> 3, ch = id & 7;   // stage0: ct=0, kq=0
            cp16(smu + SM_E + code * (EPAD * 2) + ch * 16,
                 g_Eh + (size_t)code * CD + ch * 8);
        }
        CP_COMMIT();
    }

    const uint32_t aBase = smu + SM_A + (wy * 64 + (lane & 15)) * (APAD * 2)
                           + ((lane & 16) ? 16 : 0);
    const uint32_t bBase = smu + SM_E
                           + (wx * 64 + (lane & 7) + ((lane & 16) ? 8 : 0)) * (EPAD * 2)
                           + ((lane & 8) ? 16 : 0);

    float acc[4][8][4];
    float best[8], sec[8];
    int   bidr[8];
    #pragma unroll
    for (int i = 0; i < 8; i++) { best[i] = FLT_MAX; sec[i] = FLT_MAX; bidr[i] = 0; }

    for (int s = 0; s < 32; s++) {                   // stage = ct*4 + kq
        const int ct = s >> 2, kq = s & 3, buf = s & 1;
        if ((s & 3) == 0) {
            #pragma unroll
            for (int mt = 0; mt < 4; mt++)
                #pragma unroll
                for (int nt = 0; nt < 8; nt++)
                    #pragma unroll
                    for (int c = 0; c < 4; c++) acc[mt][nt][c] = 0.f;
        }
        if (s < 31) {
            const int ns = s + 1;
            const int nct = ns >> 2, nkq = ns & 3, nbuf = ns & 1;
            #pragma unroll
            for (int it = 0; it < 8; it++) {
                const int id = it * 128 + tid;
                const int code = id >> 3, ch = id & 7;
                cp16(smu + SM_E + nbuf * E_BUF + code * (EPAD * 2) + ch * 16,
                     g_Eh + (size_t)(nct * 128 + code) * CD + nkq * 64 + ch * 8);
            }
            CP_COMMIT();
            CP_WAIT(1);
        } else {
            CP_WAIT(0);
        }
        __syncthreads();

        #pragma unroll
        for (int step = 0; step < 4; step++) {
            const int kh_abs = kq * 64 + step * 16;
            const int kh_loc = step * 16;
            uint32_t bf[8][2];
            #pragma unroll
            for (int p4 = 0; p4 < 4; p4++) {
                uint32_t r0, r1, r2, r3;
                ldsm_x4(r0, r1, r2, r3,
                        bBase + buf * E_BUF + p4 * 16 * (EPAD * 2) + kh_loc * 2);
                bf[p4 * 2][0] = r0; bf[p4 * 2][1] = r1;
                bf[p4 * 2 + 1][0] = r2; bf[p4 * 2 + 1][1] = r3;
            }
            uint32_t af[4][4];
            #pragma unroll
            for (int mt = 0; mt < 4; mt++)
                ldsm_x4(af[mt][0], af[mt][1], af[mt][2], af[mt][3],
                        aBase + mt * 16 * (APAD * 2) + kh_abs * 2);
            #pragma unroll
            for (int mt = 0; mt < 4; mt++)
                #pragma unroll
                for (int nt = 0; nt < 8; nt++)
                    mma16816(acc[mt][nt], af[mt], bf[nt]);
        }

        if ((s & 3) == 3) {
            const int k0 = ct * 128;
            #pragma unroll
            for (int mt = 0; mt < 4; mt++) {
                #pragma unroll
                for (int rsel = 0; rsel < 2; rsel++) {
                    const int bi_ = mt * 2 + rsel;
                    const int row = wy * 64 + mt * 16 + rsel * 8 + (lane >> 2);
                    const float xnv = xn_sm[row];
                    float* dr = out + OFF_D + (size_t)(n0 + row) * NK + k0;
                    #pragma unroll
                    for (int nt = 0; nt < 8; nt++) {
                        const int col0 = wx * 64 + nt * 8 + 2 * (lane & 3);
                        const float d0 = xnv + en_sm[k0 + col0]
                                       - 2.0f * acc[mt][nt][rsel * 2];
                        const float d1 = xnv + en_sm[k0 + col0 + 1]
                                       - 2.0f * acc[mt][nt][rsel * 2 + 1];
                        dr[col0] = d0;
                        dr[col0 + 1] = d1;
                        if (d0 < best[bi_]) { sec[bi_] = best[bi_]; best[bi_] = d0; bidr[bi_] = k0 + col0; }
                        else if (d0 < sec[bi_]) sec[bi_] = d0;
                        if (d1 < best[bi_]) { sec[bi_] = best[bi_]; best[bi_] = d1; bidr[bi_] = k0 + col0 + 1; }
                        else if (d1 < sec[bi_]) sec[bi_] = d1;
                    }
                }
            }
        }
        __syncthreads();
    }

    // quad reduce (lanes differing in bits 0-1 share rows): top-2 merge
    #pragma unroll
    for (int i = 0; i < 8; i++) {
        #pragma unroll
        for (int off = 1; off <= 2; off <<= 1) {
            const float v1o = __shfl_xor_sync(0xFFFFFFFFu, best[i], off);
            const int   i1o = __shfl_xor_sync(0xFFFFFFFFu, bidr[i], off);
            const float v2o = __shfl_xor_sync(0xFFFFFFFFu, sec[i], off);
            if (v1o < best[i] || (v1o == best[i] && i1o < bidr[i])) {
                sec[i]  = fminf(best[i], v2o);
                best[i] = v1o; bidr[i] = i1o;
            } else {
                sec[i] = fminf(sec[i], v1o);
            }
        }
    }
    // cross-warp reduce: wx pair shares each row group; wx==1 writes triples,
    // wx==0 merges (order-independent lexicographic, first-index-wins).
    float* sv1 = (float*)(dsm + SM_E);
    int*   si1 = (int*)(dsm + SM_E + 512);
    float* sv2 = (float*)(dsm + SM_E + 1024);
    if (wx == 1 && (lane & 3) == 0) {
        #pragma unroll
        for (int i = 0; i < 8; i++) {
            const int row = wy * 64 + (i >> 1) * 16 + (i & 1) * 8 + (lane >> 2);
            sv1[row] = best[i]; si1[row] = bidr[i]; sv2[row] = sec[i];
        }
    }
    __syncthreads();
    if (wx == 0 && (lane & 3) == 0) {
        #pragma unroll
        for (int i = 0; i < 8; i++) {
            const int row = wy * 64 + (i >> 1) * 16 + (i & 1) * 8 + (lane >> 2);
            float v1 = best[i], v2 = sec[i]; int i1 = bidr[i];
            const float o1 = sv1[row], o2 = sv2[row]; const int oi = si1[row];
            if (o1 < v1 || (o1 == v1 && oi < i1)) {
                v2 = fminf(v1, o2); v1 = o1; i1 = oi;
            } else {
                v2 = fminf(v2, o1);
            }
            const int n = n0 + row;
            g_inds[n] = i1;
            out[OFF_INDS + n] = (float)i1;
            if (v2 - v1 < GAP_THRESH) {
                int slot = atomicAdd(&g_nflag, 1);
                g_flag[slot] = n;
            }
        }
    }
}

// ---------------------------------------------------------------------------
// Refine v2: candidates from the written d row within CAND_MARGIN of its min,
// recomputed exactly in fp32; lexicographic (d, k) min. ~10KB/point traffic.
// ---------------------------------------------------------------------------
__global__ __launch_bounds__(256) void vq_refine(const float* __restrict__ z,
                                                 const float* __restrict__ E,
                                                 float* __restrict__ out) {
    __shared__ float zs[256];
    __shared__ float rv[8];
    __shared__ int   ri[8];
    __shared__ int   cand[64];
    __shared__ int   ncand;
    const int nf = g_nflag;
    const int tid = threadIdx.x, w = tid >> 5, lane = tid & 31;

    for (int f = blockIdx.x; f < nf; f += gridDim.x) {
        const int p = g_flag[f];
        const int b = p >> 13, thw = p & (ZTHW - 1);
        const float* zp = z + (size_t)b * CD * ZTHW + thw;
        zs[tid] = zp[(size_t)tid * ZTHW];
        if (tid == 0) ncand = 0;
        __syncthreads();

        const float* drow = out + OFF_D + (size_t)p * NK;
        float bv = FLT_MAX;
        float dv[4];
        #pragma unroll
        for (int j = 0; j < 4; j++) {
            dv[j] = drow[j * 256 + tid];
            bv = fminf(bv, dv[j]);
        }
        #pragma unroll
        for (int off = 16; off; off >>= 1)
            bv = fminf(bv, __shfl_xor_sync(0xFFFFFFFFu, bv, off));
        if (lane == 0) rv[w] = bv;
        __syncthreads();
        if (tid == 0) {
            float v = rv[0];
            #pragma unroll
            for (int w2 = 1; w2 < 8; w2++) v = fminf(v, rv[w2]);
            rv[0] = v;
        }
        __syncthreads();
        const float vmin = rv[0];

        #pragma unroll
        for (int j = 0; j < 4; j++) {
            if (dv[j] < vmin + CAND_MARGIN) {
                const int s = atomicAdd(&ncand, 1);
                if (s < 64) cand[s] = j * 256 + tid;
            }
        }
        __syncthreads();
        const int nc = min(ncand, 64);

        float cbv = FLT_MAX; int cbi = 0x7FFFFFFF;
        const float xn = xnorm_of(p);
        for (int ci = w; ci < nc; ci += 8) {
            const int k = cand[ci];
            const float* er = E + (size_t)k * CD;
            float dot = 0.f;
            #pragma unroll
            for (int i = 0; i < 8; i++)
                dot = fmaf(er[lane + 32 * i], zs[lane + 32 * i], dot);
            #pragma unroll
            for (int off = 16; off; off >>= 1)
                dot += __shfl_xor_sync(0xFFFFFFFFu, dot, off);
            const float d = xn + g_enorm[k] - 2.0f * dot;
            if (d < cbv || (d == cbv && k < cbi)) { cbv = d; cbi = k; }
        }
        if (lane == 0) { rv[w] = cbv; ri[w] = cbi; }
        __syncthreads();
        if (tid == 0) {
            float v = rv[0]; int id = ri[0];
            #pragma unroll
            for (int w2 = 1; w2 < 8; w2++)
                if (rv[w2] < v || (rv[w2] == v && ri[w2] < id)) { v = rv[w2]; id = ri[w2]; }
            g_inds[p] = id;
            out[OFF_INDS + p] = (float)id;
        }
        __syncthreads();
    }
}

// ---------------------------------------------------------------------------
// Gather z_q, z_q_ste = z + (z_q - z), deterministic loss partials.
// ---------------------------------------------------------------------------
__global__ __launch_bounds__(256) void vq_out(const float* __restrict__ z,
                                              const float* __restrict__ E,
                                              float* __restrict__ out) {
    int t = blockIdx.x * blockDim.x + threadIdx.x;
    int p = t >> 2, q = t & 3;
    int b = p >> 13, thw = p & (ZTHW - 1);
    const float* zp = z + (size_t)b * CD * ZTHW + thw;
    float* op = out + OFF_ZQ + (size_t)b * CD * ZTHW + thw;
    int row = g_inds[p];
    const float4* er = (const float4*)(E + (size_t)row * CD + q * 64);

    float local = 0.f;
    #pragma unroll 4
    for (int c4 = 0; c4 < 16; c4++) {
        float4 e4 = er[c4];
        float ev[4] = {e4.x, e4.y, e4.z, e4.w};
        #pragma unroll
        for (int j = 0; j < 4; j++) {
            int c = q * 64 + c4 * 4 + j;
            float zv = zp[(size_t)c * ZTHW];
            float tt = __fsub_rn(ev[j], zv);
            op[(size_t)c * ZTHW] = __fadd_rn(zv, tt);
            local = fmaf(tt, tt, local);
        }
    }
    #pragma unroll
    for (int off = 16; off; off >>= 1) local += __shfl_xor_sync(0xFFFFFFFFu, local, off);
    __shared__ float ws[8];
    int lane = threadIdx.x & 31, w = threadIdx.x >> 5;
    if (lane == 0) ws[w] = local;
    __syncthreads();
    if (threadIdx.x == 0) {
        double s = 0.0;
        #pragma unroll
        for (int i = 0; i < 8; i++) s += (double)ws[i];
        g_part[blockIdx.x] = s;
    }
}

__global__ void vq_finalize(float* __restrict__ out, int npart) {
    if (threadIdx.x == 0 && blockIdx.x == 0) {
        double s = 0.0;
        for (int i = 0; i < npart; i++) s += g_part[i];
        out[OFF_LOSS] = (float)(1.25 * s / 8388608.0);
    }
}

// ---------------------------------------------------------------------------
extern "C" void kernel_launch(void* const* d_in, const int* in_sizes, int n_in,
                              void* d_out, int out_size) {
    const float* z = (const float*)d_in[0];
    const float* E = (const float*)d_in[1];
    float* out = (float*)d_out;

    conv_z<<<2048, 256>>>(z);             // also emits xnorm partials
    conv_E<<<128, 256>>>(E);              // also emits enorm, zeroes g_nflag

    cudaFuncSetAttribute(vq_gemm_mma, cudaFuncAttributeMaxDynamicSharedMemorySize, SM_TOT);
    vq_gemm_mma<<<NPT / 128, 128, SM_TOT>>>(out);

    vq_refine<<<592, 256>>>(z, E, out);
    vq_out<<<512, 256>>>(z, E, out);
    vq_finalize<<<1, 32>>>(out, 512);
}